// round 5
// baseline (speedup 1.0000x reference)
#include <cuda_runtime.h>
#include <cstdint>

// ---------------------------------------------------------------------------
// TorchNeighborList: N=4096 atoms, no PBC. Output layout (as float32):
//   [0,      M)   idx_i   (valid prefix [0,T), sentinel N in [T,M))
//   [M,     2M)   idx_j   (same split)
//   [2M,    5M)   Rij     (valid prefix [0,3T), zeros after)
//   [5M,    8M)   cell_offset (ALL zeros, independent of T)
//   [8M,    9M)   mask    (1.0 in [0,T), 0.0 after)
//   [9M]          num_pairs = T
// where M = 2P = N*(N-1), T = number of in-cutoff directed pairs.
//
// Ordering reproduced analytically: centers ascending; within center k,
// neighbors in order j = (k+t) mod N for t = 1..N-1 (exactly the reference's
// stable argsort over concat(triu_i, triu_j)).
//
// Schedule:
//   L1 count+zero : warp-per-(center,chunk) counts (caching ballot masks),
//                   PLUS blocks zeroing the T-independent cell_offset region.
//   L2 scan       : order-preserving exclusive scan -> offsets, T.
//   L3 epilogue   : mask-driven valid emit || branch-free region-partitioned
//                   padding streams (address-disjoint once T is known).
// ---------------------------------------------------------------------------

#define CHUNK 512
#define MPW   (CHUNK / 32)          // masks per warp (16)
#define MAX_SEG 65536

__device__ int g_counts[MAX_SEG];
__device__ int g_offsets[MAX_SEG];
__device__ unsigned g_masks[MAX_SEG * MPW];
__device__ int g_total;

// exact (non-contracted) squared distance, matching jnp.linalg.norm assoc order
__device__ __forceinline__ float dist2(float dx, float dy, float dz) {
    return __fadd_rn(__fadd_rn(__fmul_rn(dx, dx), __fmul_rn(dy, dy)),
                     __fmul_rn(dz, dz));
}

// -------- Kernel 1: counts (+mask cache) + cell_offset zeroing ------------
__global__ __launch_bounds__(256) void count_zero_kernel(
    const float* __restrict__ pos, float* __restrict__ out,
    size_t M, int N, int C, int FB) {
    if ((int)blockIdx.x < FB) {
        int warp = (int)((blockIdx.x * (size_t)blockDim.x + threadIdx.x) >> 5);
        int lane = threadIdx.x & 31;
        if (warp >= N * C) return;
        int k = warp / C;
        int c = warp - k * C;

        const float* pk = pos + 3 * (size_t)k;
        float xk = __ldg(pk), yk = __ldg(pk + 1), zk = __ldg(pk + 2);

        int cnt = 0;
        int tbase = c * CHUNK;
#pragma unroll 4
        for (int u = 0; u < MPW; u++) {
            int t = tbase + u * 32 + lane;
            bool valid = false;
            if (t > 0 && t < N) {
                int j = k + t;
                if (j >= N) j -= N;
                const float* pj = pos + 3 * (size_t)j;
                float dx = __fsub_rn(__ldg(pj),     xk);
                float dy = __fsub_rn(__ldg(pj + 1), yk);
                float dz = __fsub_rn(__ldg(pj + 2), zk);
                valid = dist2(dx, dy, dz) < 25.0f;
            }
            unsigned m = __ballot_sync(0xffffffffu, valid);
            if (lane == 0) g_masks[warp * MPW + u] = m;
            cnt += __popc(m);
        }
        if (lane == 0) g_counts[warp] = cnt;
    } else {
        // cell_offset region: [5M, 8M); M % 4 == 0 so float4-aligned
        float4* __restrict__ out4 = (float4*)out;
        const float4 zv = make_float4(0.f, 0.f, 0.f, 0.f);
        size_t lo4 = (5 * M) / 4, hi4 = (8 * M) / 4;
        int pb = (int)blockIdx.x - FB;
        int npb = (int)gridDim.x - FB;
        size_t stride = (size_t)npb * blockDim.x;
        for (size_t i = lo4 + (size_t)pb * blockDim.x + threadIdx.x; i < hi4;
             i += stride)
            out4[i] = zv;
    }
}

// -------- Kernel 2: exclusive scan over (center,chunk) counts -------------
__global__ __launch_bounds__(1024) void scan_kernel(float* __restrict__ out,
                                                    size_t M, int S) {
    __shared__ int s[1024];
    int t = threadIdx.x;
    int per = (S + 1023) / 1024;
    int sum = 0;
    for (int u = 0; u < per; u++) {
        int i = t * per + u;
        if (i < S) sum += g_counts[i];
    }
    s[t] = sum;
    __syncthreads();
    for (int off = 1; off < 1024; off <<= 1) {
        int v = (t >= off) ? s[t - off] : 0;
        __syncthreads();
        s[t] += v;
        __syncthreads();
    }
    int base = s[t] - sum;
    for (int u = 0; u < per; u++) {
        int i = t * per + u;
        if (i < S) {
            g_offsets[i] = base;
            base += g_counts[i];
        }
    }
    if (t == 1023) {
        g_total = s[1023];
        out[9 * M] = (float)s[1023];  // num_pairs
    }
}

// -------- Kernel 3: fused epilogue ----------------------------------------
// Blocks [0, FB): mask-driven valid emit (no distance recompute for invalid).
// Blocks [FB, ...): 4 groups of pad blocks, one per region, each a
//                   branch-free float4 stream over its padding suffix.
#define PG_IDXI 682
#define PG_IDXJ 682
#define PG_RIJ  2048
#define PG_MASK 684
#define PAD_BLOCKS (PG_IDXI + PG_IDXJ + PG_RIJ + PG_MASK)  // 4096

__global__ __launch_bounds__(256) void epilogue(const float* __restrict__ pos,
                                                float* __restrict__ out,
                                                size_t M, int N, int C, int FB) {
    if ((int)blockIdx.x < FB) {
        // ---- valid-entry emit from cached masks ----
        int warp = (int)((blockIdx.x * (size_t)blockDim.x + threadIdx.x) >> 5);
        int lane = threadIdx.x & 31;
        if (warp >= N * C) return;
        int k = warp / C;
        int c = warp - k * C;

        const float* pk = pos + 3 * (size_t)k;
        float xk = __ldg(pk), yk = __ldg(pk + 1), zk = __ldg(pk + 2);
        float fk = (float)k;
        int base = g_offsets[warp];

        float* __restrict__ idx_i = out;
        float* __restrict__ idx_j = out + M;
        float* __restrict__ rij   = out + 2 * M;
        float* __restrict__ maskp = out + 8 * M;

#pragma unroll 4
        for (int u = 0; u < MPW; u++) {
            unsigned m = g_masks[warp * MPW + u];
            if ((m >> lane) & 1u) {
                int t = c * CHUNK + u * 32 + lane;
                int j = k + t;
                if (j >= N) j -= N;
                const float* pj = pos + 3 * (size_t)j;
                float dx = __fsub_rn(__ldg(pj),     xk);
                float dy = __fsub_rn(__ldg(pj + 1), yk);
                float dz = __fsub_rn(__ldg(pj + 2), zk);
                int p = base + __popc(m & ((1u << lane) - 1u));
                idx_i[p] = fk;
                idx_j[p] = (float)j;
                rij[3 * (size_t)p + 0] = dx;
                rij[3 * (size_t)p + 1] = dy;
                rij[3 * (size_t)p + 2] = dz;
                maskp[p] = 1.0f;
            }
            base += __popc(m);
        }
    } else {
        // ---- branch-free padding streams, one region per block group ----
        size_t T = (size_t)g_total;
        int pb = (int)blockIdx.x - FB;

        size_t rbase, rlen, bound;  // region base, region length, valid bound
        float val;
        int gb, gn;                 // group-local block id, group size
        if (pb < PG_IDXI) {
            rbase = 0;     rlen = M;     bound = T;     val = (float)N;
            gb = pb;                          gn = PG_IDXI;
        } else if (pb < PG_IDXI + PG_IDXJ) {
            rbase = M;     rlen = M;     bound = T;     val = (float)N;
            gb = pb - PG_IDXI;                gn = PG_IDXJ;
        } else if (pb < PG_IDXI + PG_IDXJ + PG_RIJ) {
            rbase = 2 * M; rlen = 3 * M; bound = 3 * T; val = 0.f;
            gb = pb - PG_IDXI - PG_IDXJ;      gn = PG_RIJ;
        } else {
            rbase = 8 * M; rlen = M;     bound = T;     val = 0.f;
            gb = pb - PG_IDXI - PG_IDXJ - PG_RIJ; gn = PG_MASK;
        }

        // boundary scalars up to the next float4 alignment (<=3 per region)
        size_t aligned = (bound + 3) & ~(size_t)3;
        if (gb == 0 && threadIdx.x < 4) {
            size_t e = bound + threadIdx.x;
            if (e < aligned && e < rlen) out[rbase + e] = val;
        }

        // branch-free vector stream over [aligned, rlen)
        float4* __restrict__ out4 = (float4*)(out + rbase);
        const float4 v4 = make_float4(val, val, val, val);
        size_t lo4 = aligned / 4, hi4 = rlen / 4;
        size_t stride = (size_t)gn * blockDim.x;
        for (size_t i = lo4 + (size_t)gb * blockDim.x + threadIdx.x; i < hi4;
             i += stride)
            out4[i] = v4;
    }
}

// ---------------------------------------------------------------------------
extern "C" void kernel_launch(void* const* d_in, const int* in_sizes, int n_in,
                              void* d_out, int out_size) {
    const float* pos = (const float*)d_in[0];
    int N = in_sizes[0] / 3;                   // 4096
    size_t M = ((size_t)out_size - 1) / 9;     // 2P = N*(N-1)
    float* out = (float*)d_out;

    int C = (N + CHUNK - 1) / CHUNK;           // 8 chunks per center
    int S = N * C;                             // 32768 segments

    int fill_blocks = (S * 32 + 255) / 256;    // 4096: warp per segment
    int zero_blocks = 2048;                    // cell_offset zeroing

    count_zero_kernel<<<fill_blocks + zero_blocks, 256>>>(pos, out, M, N, C,
                                                          fill_blocks);
    scan_kernel<<<1, 1024>>>(out, M, S);
    epilogue<<<fill_blocks + PAD_BLOCKS, 256>>>(pos, out, M, N, C, fill_blocks);
}

// round 6
// speedup vs baseline: 1.1539x; 1.1539x over previous
#include <cuda_runtime.h>
#include <cstdint>

// ---------------------------------------------------------------------------
// TorchNeighborList: N=4096 atoms, no PBC. Output layout (as float32):
//   [0,      M)   idx_i   (valid prefix [0,T), sentinel N in [T,M))
//   [M,     2M)   idx_j   (same split)
//   [2M,    5M)   Rij     (valid prefix [0,3T), zeros after)
//   [5M,    8M)   cell_offset (all zeros)
//   [8M,    9M)   mask    (1.0 in [0,T), 0.0 after)
//   [9M]          num_pairs = T
// where M = 2P = N*(N-1), T = number of in-cutoff directed pairs (~325k).
//
// Ordering reproduced analytically: centers ascending; within center k,
// neighbors in order j = (k+t) mod N for t = 1..N-1 (exactly the reference's
// stable argsort over concat(triu_i, triu_j)).
//
// Schedule (fill is the long pole; everything else hides inside it):
//   L1 fused : blocks [0,FB)   = uniform default fill of ALL 9M floats
//              blocks [FB,+4K) = warp-per-(center,chunk) counts + ballot cache
//   L2 scan  : order-preserving exclusive scan -> offsets, T (out[9M])
//   L3 emit  : mask-driven compacted valid emit (~11 MB scattered writes),
//              overwrites defaults in the valid prefix.
// ---------------------------------------------------------------------------

#define CHUNK 512
#define MPW   (CHUNK / 32)          // ballots per segment (16)
#define MAX_SEG 65536

__device__ int g_counts[MAX_SEG];
__device__ int g_offsets[MAX_SEG];
__device__ unsigned g_masks[MAX_SEG * MPW];
__device__ int g_total;

// exact (non-contracted) squared distance, matching jnp.linalg.norm assoc order
__device__ __forceinline__ float dist2(float dx, float dy, float dz) {
    return __fadd_rn(__fadd_rn(__fmul_rn(dx, dx), __fmul_rn(dy, dy)),
                     __fmul_rn(dz, dz));
}

// -------- Kernel 1: uniform default fill || counts ------------------------
__global__ __launch_bounds__(256) void fill_count_kernel(
    const float* __restrict__ pos, float* __restrict__ out,
    size_t M, int N, int C, int FB) {
    if ((int)blockIdx.x < FB) {
        // ---- uniform fill: sentinel over [0,2M), zero over [2M,9M) ----
        float4* __restrict__ out4 = (float4*)out;
        const float sn = (float)N;
        const float4 sv = make_float4(sn, sn, sn, sn);
        const float4 zv = make_float4(0.f, 0.f, 0.f, 0.f);
        size_t n4 = (9 * M) / 4;
        size_t idx_end4 = (2 * M) / 4;
        size_t stride = (size_t)FB * 512;           // 2 vec4 per thread/iter
        size_t base = (size_t)blockIdx.x * 512 + threadIdx.x;
        for (size_t i = base; i < n4; i += stride) {
            out4[i] = (i < idx_end4) ? sv : zv;
            size_t i2 = i + 256;
            if (i2 < n4) out4[i2] = (i2 < idx_end4) ? sv : zv;
        }
    } else {
        // ---- counts + ballot cache: warp per (center,chunk) ----
        int warp = (int)((((size_t)blockIdx.x - FB) * blockDim.x + threadIdx.x) >> 5);
        int lane = threadIdx.x & 31;
        if (warp >= N * C) return;
        int k = warp / C;
        int c = warp - k * C;

        const float* pk = pos + 3 * (size_t)k;
        float xk = __ldg(pk), yk = __ldg(pk + 1), zk = __ldg(pk + 2);

        int cnt = 0;
        int tbase = c * CHUNK;
#pragma unroll 4
        for (int u = 0; u < MPW; u++) {
            int t = tbase + u * 32 + lane;
            bool valid = false;
            if (t > 0 && t < N) {
                int j = k + t;
                if (j >= N) j -= N;
                const float* pj = pos + 3 * (size_t)j;
                float dx = __fsub_rn(__ldg(pj),     xk);
                float dy = __fsub_rn(__ldg(pj + 1), yk);
                float dz = __fsub_rn(__ldg(pj + 2), zk);
                valid = dist2(dx, dy, dz) < 25.0f;
            }
            unsigned m = __ballot_sync(0xffffffffu, valid);
            if (lane == 0) g_masks[warp * MPW + u] = m;
            cnt += __popc(m);
        }
        if (lane == 0) g_counts[warp] = cnt;
    }
}

// -------- Kernel 2: exclusive scan over (center,chunk) counts -------------
__global__ __launch_bounds__(1024) void scan_kernel(float* __restrict__ out,
                                                    size_t M, int S) {
    __shared__ int s[1024];
    int t = threadIdx.x;
    int per = (S + 1023) / 1024;
    int sum = 0;
    for (int u = 0; u < per; u++) {
        int i = t * per + u;
        if (i < S) sum += g_counts[i];
    }
    s[t] = sum;
    __syncthreads();
    for (int off = 1; off < 1024; off <<= 1) {
        int v = (t >= off) ? s[t - off] : 0;
        __syncthreads();
        s[t] += v;
        __syncthreads();
    }
    int base = s[t] - sum;
    for (int u = 0; u < per; u++) {
        int i = t * per + u;
        if (i < S) {
            g_offsets[i] = base;
            base += g_counts[i];
        }
    }
    if (t == 1023) {
        g_total = s[1023];
        out[9 * M] = (float)s[1023];  // num_pairs
    }
}

// -------- Kernel 3: mask-driven compacted valid emit ----------------------
__global__ __launch_bounds__(256) void emit_kernel(const float* __restrict__ pos,
                                                   float* __restrict__ out,
                                                   size_t M, int N, int C) {
    int warp = (int)((blockIdx.x * (size_t)blockDim.x + threadIdx.x) >> 5);
    int lane = threadIdx.x & 31;
    if (warp >= N * C) return;
    int k = warp / C;
    int c = warp - k * C;

    const float* pk = pos + 3 * (size_t)k;
    float xk = __ldg(pk), yk = __ldg(pk + 1), zk = __ldg(pk + 2);
    float fk = (float)k;
    int base = g_offsets[warp];

    float* __restrict__ idx_i = out;
    float* __restrict__ idx_j = out + M;
    float* __restrict__ rij   = out + 2 * M;
    float* __restrict__ maskp = out + 8 * M;

#pragma unroll 4
    for (int u = 0; u < MPW; u++) {
        unsigned m = g_masks[warp * MPW + u];
        if ((m >> lane) & 1u) {
            int t = c * CHUNK + u * 32 + lane;
            int j = k + t;
            if (j >= N) j -= N;
            const float* pj = pos + 3 * (size_t)j;
            float dx = __fsub_rn(__ldg(pj),     xk);   // pos[j]-pos[k]
            float dy = __fsub_rn(__ldg(pj + 1), yk);
            float dz = __fsub_rn(__ldg(pj + 2), zk);
            int p = base + __popc(m & ((1u << lane) - 1u));
            idx_i[p] = fk;
            idx_j[p] = (float)j;
            rij[3 * (size_t)p + 0] = dx;
            rij[3 * (size_t)p + 1] = dy;
            rij[3 * (size_t)p + 2] = dz;
            maskp[p] = 1.0f;
        }
        base += __popc(m);
    }
}

// ---------------------------------------------------------------------------
extern "C" void kernel_launch(void* const* d_in, const int* in_sizes, int n_in,
                              void* d_out, int out_size) {
    const float* pos = (const float*)d_in[0];
    int N = in_sizes[0] / 3;                   // 4096
    size_t M = ((size_t)out_size - 1) / 9;     // 2P = N*(N-1)
    float* out = (float*)d_out;

    int C = (N + CHUNK - 1) / CHUNK;           // 8 chunks per center
    int S = N * C;                             // 32768 segments

    int count_blocks = (S * 32 + 255) / 256;   // 4096: warp per segment
    int fill_blocks  = 4736;                   // fill first -> starts in wave 1

    fill_count_kernel<<<fill_blocks + count_blocks, 256>>>(pos, out, M, N, C,
                                                           fill_blocks);
    scan_kernel<<<1, 1024>>>(out, M, S);
    emit_kernel<<<count_blocks, 256>>>(pos, out, M, N, C);
}

// round 7
// speedup vs baseline: 1.6063x; 1.3920x over previous
#include <cuda_runtime.h>
#include <cstdint>

// ---------------------------------------------------------------------------
// TorchNeighborList: N=4096 atoms, no PBC. Output layout (as float32):
//   [0,      M)   idx_i   (valid prefix [0,T), sentinel N in [T,M))
//   [M,     2M)   idx_j   (same split)
//   [2M,    5M)   Rij     (valid prefix [0,3T), zeros after)
//   [5M,    8M)   cell_offset (all zeros)
//   [8M,    9M)   mask    (1.0 in [0,T), 0.0 after)
//   [9M]          num_pairs = T
// where M = 2P = N*(N-1), T = number of in-cutoff directed pairs (~325k).
//
// Ordering reproduced analytically: centers ascending; within center k,
// neighbors in order j = (k+t) mod N for t = 1..N-1 (exactly the reference's
// stable argsort over concat(triu_i, triu_j)).
//
// Schedule:
//   L1 fused : blocks [0,FB)   = uniform default fill of ALL 9M floats
//              blocks [FB,+4K) = warp-per-(center,chunk) counts + ballot cache
//   L2 scan  : coalesced shfl-based exclusive scan -> g_offsets, T
//   L3 emit  : thread-per-valid-pair (binary search segment, nth-bit in
//              ballot) -> coalesced compacted stores at [0,T)
// ---------------------------------------------------------------------------

#define CHUNK 512
#define MPW   (CHUNK / 32)          // ballots per segment (16)
#define MAX_SEG 65536

__device__ int g_counts[MAX_SEG];
__device__ int g_offsets[MAX_SEG];
__device__ unsigned g_masks[MAX_SEG * MPW];
__device__ int g_total;

// exact (non-contracted) squared distance, matching jnp.linalg.norm assoc order
__device__ __forceinline__ float dist2(float dx, float dy, float dz) {
    return __fadd_rn(__fadd_rn(__fmul_rn(dx, dx), __fmul_rn(dy, dy)),
                     __fmul_rn(dz, dz));
}

// -------- Kernel 1: uniform default fill || counts ------------------------
__global__ __launch_bounds__(256) void fill_count_kernel(
    const float* __restrict__ pos, float* __restrict__ out,
    size_t M, int N, int C, int FB) {
    if ((int)blockIdx.x < FB) {
        // ---- uniform fill: sentinel over [0,2M), zero over [2M,9M) ----
        float4* __restrict__ out4 = (float4*)out;
        const float sn = (float)N;
        const float4 sv = make_float4(sn, sn, sn, sn);
        const float4 zv = make_float4(0.f, 0.f, 0.f, 0.f);
        size_t n4 = (9 * M) / 4;
        size_t idx_end4 = (2 * M) / 4;
        size_t stride = (size_t)FB * 512;           // 2 vec4 per thread/iter
        size_t base = (size_t)blockIdx.x * 512 + threadIdx.x;
        for (size_t i = base; i < n4; i += stride) {
            out4[i] = (i < idx_end4) ? sv : zv;
            size_t i2 = i + 256;
            if (i2 < n4) out4[i2] = (i2 < idx_end4) ? sv : zv;
        }
    } else {
        // ---- counts + ballot cache: warp per (center,chunk) ----
        int warp = (int)((((size_t)blockIdx.x - FB) * blockDim.x + threadIdx.x) >> 5);
        int lane = threadIdx.x & 31;
        if (warp >= N * C) return;
        int k = warp / C;
        int c = warp - k * C;

        const float* pk = pos + 3 * (size_t)k;
        float xk = __ldg(pk), yk = __ldg(pk + 1), zk = __ldg(pk + 2);

        int cnt = 0;
        int tbase = c * CHUNK;
#pragma unroll 4
        for (int u = 0; u < MPW; u++) {
            int t = tbase + u * 32 + lane;
            bool valid = false;
            if (t > 0 && t < N) {
                int j = k + t;
                if (j >= N) j -= N;
                const float* pj = pos + 3 * (size_t)j;
                float dx = __fsub_rn(__ldg(pj),     xk);
                float dy = __fsub_rn(__ldg(pj + 1), yk);
                float dz = __fsub_rn(__ldg(pj + 2), zk);
                valid = dist2(dx, dy, dz) < 25.0f;
            }
            unsigned m = __ballot_sync(0xffffffffu, valid);
            if (lane == 0) g_masks[warp * MPW + u] = m;
            cnt += __popc(m);
        }
        if (lane == 0) g_counts[warp] = cnt;
    }
}

// -------- Kernel 2: coalesced exclusive scan (1024 thr, shfl) -------------
__global__ __launch_bounds__(1024) void scan_kernel(float* __restrict__ out,
                                                    size_t M, int S) {
    __shared__ int wsum[32];
    __shared__ int wbase[32];
    __shared__ int s_tile_total;
    int t = threadIdx.x;
    int warp = t >> 5, lane = t & 31;
    int running = 0;

    for (int tile = 0; tile < S; tile += 1024) {
        int i = tile + t;
        int c = (i < S) ? g_counts[i] : 0;

        // warp-inclusive scan
        int incl = c;
#pragma unroll
        for (int o = 1; o < 32; o <<= 1) {
            int v = __shfl_up_sync(0xffffffffu, incl, o);
            if (lane >= o) incl += v;
        }
        if (lane == 31) wsum[warp] = incl;
        __syncthreads();

        if (warp == 0) {
            int v = wsum[lane];
            int winc = v;
#pragma unroll
            for (int o = 1; o < 32; o <<= 1) {
                int x = __shfl_up_sync(0xffffffffu, winc, o);
                if (lane >= o) winc += x;
            }
            wbase[lane] = winc - v;  // exclusive warp base
            if (lane == 31) s_tile_total = winc;
        }
        __syncthreads();

        if (i < S) g_offsets[i] = running + wbase[warp] + (incl - c);
        running += s_tile_total;
        __syncthreads();  // protect wsum/wbase reuse next tile
    }
    if (t == 0) {
        g_total = running;
        out[9 * M] = (float)running;  // num_pairs
    }
}

// -------- Kernel 3: thread-per-valid-pair emit ----------------------------
__global__ __launch_bounds__(256) void emit_kernel(const float* __restrict__ pos,
                                                   float* __restrict__ out,
                                                   size_t M, int N, int C, int S) {
    int T = g_total;
    float* __restrict__ idx_i = out;
    float* __restrict__ idx_j = out + M;
    float* __restrict__ rij   = out + 2 * M;
    float* __restrict__ maskp = out + 8 * M;

    int stride = (int)(gridDim.x * blockDim.x);
    for (int p = (int)(blockIdx.x * blockDim.x + threadIdx.x); p < T;
         p += stride) {
        // binary search: largest w with g_offsets[w] <= p
        int lo = 0, hi = S;
        while (hi - lo > 1) {
            int mid = (lo + hi) >> 1;
            if (g_offsets[mid] <= p) lo = mid; else hi = mid;
        }
        int w = lo;
        int r = p - g_offsets[w];          // rank within segment
        int k = w / C;
        int c = w - k * C;

        // locate the ballot containing rank r
        int u = 0;
        unsigned m;
        for (;;) {
            m = g_masks[w * MPW + u];
            int cnt = __popc(m);
            if (r < cnt) break;
            r -= cnt;
            u++;
        }
        // r-th set bit of m
        unsigned mm = m;
        for (int q = 0; q < r; q++) mm &= mm - 1;
        int lane = __ffs(mm) - 1;

        int t = c * CHUNK + u * 32 + lane;
        int j = k + t;
        if (j >= N) j -= N;

        const float* pk = pos + 3 * (size_t)k;
        const float* pj = pos + 3 * (size_t)j;
        float dx = __fsub_rn(__ldg(pj),     __ldg(pk));      // pos[j]-pos[k]
        float dy = __fsub_rn(__ldg(pj + 1), __ldg(pk + 1));
        float dz = __fsub_rn(__ldg(pj + 2), __ldg(pk + 2));

        idx_i[p] = (float)k;
        idx_j[p] = (float)j;
        rij[3 * (size_t)p + 0] = dx;
        rij[3 * (size_t)p + 1] = dy;
        rij[3 * (size_t)p + 2] = dz;
        maskp[p] = 1.0f;
    }
}

// ---------------------------------------------------------------------------
extern "C" void kernel_launch(void* const* d_in, const int* in_sizes, int n_in,
                              void* d_out, int out_size) {
    const float* pos = (const float*)d_in[0];
    int N = in_sizes[0] / 3;                   // 4096
    size_t M = ((size_t)out_size - 1) / 9;     // 2P = N*(N-1)
    float* out = (float*)d_out;

    int C = (N + CHUNK - 1) / CHUNK;           // 8 chunks per center
    int S = N * C;                             // 32768 segments

    int count_blocks = (S * 32 + 255) / 256;   // 4096: warp per segment
    int fill_blocks  = 4736;                   // fill first -> starts in wave 1

    fill_count_kernel<<<fill_blocks + count_blocks, 256>>>(pos, out, M, N, C,
                                                           fill_blocks);
    scan_kernel<<<1, 1024>>>(out, M, S);
    emit_kernel<<<2048, 256>>>(pos, out, M, N, C, S);
}